// round 9
// baseline (speedup 1.0000x reference)
#include <cuda_runtime.h>

// DempsterSchaferCombine — algebraically reduced to a pure elementwise stream:
//   out = (a1-1)*(a2-1)/21 + a1 + a2 - 1
// (Dirichlet strengths S1,S2 and the conflict denom cancel exactly; rel_err
// vs the full reference path is ~8e-8.)
//
// R9 (convergence): R7/R8 structure — one-shot grid, 128-thr CTAs, one
// 256-bit v8 chunk per thread per array, branch-free exact tiling — with
// 32-bit element indexing (total 44M elements < 2^31) to drop the
// IMAD.WIDE addressing chains that showed as alu 4%.
// Measured ceiling: DRAM counters pinned at 85.5-86.7% across every one-shot
// variant; 528 MB moved in ~70us = 7.5 TB/s effective.

#define INV_C (1.0f / 21.0f)

__device__ __forceinline__ void ld256_cs(const float* p, float v[8]) {
    asm volatile(
        "ld.global.cs.v8.f32 {%0,%1,%2,%3,%4,%5,%6,%7}, [%8];"
        : "=f"(v[0]), "=f"(v[1]), "=f"(v[2]), "=f"(v[3]),
          "=f"(v[4]), "=f"(v[5]), "=f"(v[6]), "=f"(v[7])
        : "l"(p));
}

__device__ __forceinline__ void st256_cs(float* p, const float v[8]) {
    asm volatile(
        "st.global.cs.v8.f32 [%0], {%1,%2,%3,%4,%5,%6,%7,%8};"
        :: "l"(p),
           "f"(v[0]), "f"(v[1]), "f"(v[2]), "f"(v[3]),
           "f"(v[4]), "f"(v[5]), "f"(v[6]), "f"(v[7])
        : "memory");
}

// Exact path: one 8-float chunk per thread, no predicates, 32-bit indexing.
// Requires n % (128*8) == 0, n < 2^31, 32B-aligned pointers.
__global__ __launch_bounds__(128, 16) void ds_combine_v8(
    const float* __restrict__ a1,
    const float* __restrict__ a2,
    float* __restrict__ out)
{
    unsigned int base = (blockIdx.x * 128u + threadIdx.x) * 8u;

    float x[8], y[8], r[8];
    ld256_cs(a1 + base, x);
    ld256_cs(a2 + base, y);

#pragma unroll
    for (int k = 0; k < 8; k++)
        r[k] = fmaf((x[k] - 1.0f) * (y[k] - 1.0f), INV_C, x[k] + y[k] - 1.0f);

    st256_cs(out + base, r);
}

__device__ __forceinline__ float4 ds4(float4 x, float4 y) {
    float4 r;
    r.x = fmaf((x.x - 1.0f) * (y.x - 1.0f), INV_C, x.x + y.x - 1.0f);
    r.y = fmaf((x.y - 1.0f) * (y.y - 1.0f), INV_C, x.y + y.y - 1.0f);
    r.z = fmaf((x.z - 1.0f) * (y.z - 1.0f), INV_C, x.z + y.z - 1.0f);
    r.w = fmaf((x.w - 1.0f) * (y.w - 1.0f), INV_C, x.w + y.w - 1.0f);
    return r;
}

// Guarded fallback (float4) for shapes not divisible by 1024 floats/block.
__global__ __launch_bounds__(256, 8) void ds_combine_guarded(
    const float4* __restrict__ a1,
    const float4* __restrict__ a2,
    float4* __restrict__ out,
    int n4)
{
    int i0 = blockIdx.x * 512 + threadIdx.x;
    int i1 = i0 + 256;
    if (i1 < n4) {
        float4 x0 = __ldcs(a1 + i0);
        float4 x1 = __ldcs(a1 + i1);
        float4 y0 = __ldcs(a2 + i0);
        float4 y1 = __ldcs(a2 + i1);
        __stcs(out + i0, ds4(x0, y0));
        __stcs(out + i1, ds4(x1, y1));
    } else if (i0 < n4) {
        float4 x0 = __ldcs(a1 + i0);
        float4 y0 = __ldcs(a2 + i0);
        __stcs(out + i0, ds4(x0, y0));
    }
}

// Scalar tail for n % 4 != 0 (not hit for this shape; kept for safety).
__global__ void ds_combine_tail(
    const float* __restrict__ a1,
    const float* __restrict__ a2,
    float* __restrict__ out,
    int start, int n)
{
    int i = start + blockIdx.x * blockDim.x + threadIdx.x;
    if (i >= n) return;
    float x = a1[i], y = a2[i];
    out[i] = fmaf((x - 1.0f) * (y - 1.0f), INV_C, x + y - 1.0f);
}

extern "C" void kernel_launch(void* const* d_in, const int* in_sizes, int n_in,
                              void* d_out, int out_size)
{
    const float* a1 = (const float*)d_in[0];
    const float* a2 = (const float*)d_in[1];
    float* out = (float*)d_out;

    int n = out_size;                    // 8*21*512*512 = 44,040,192
    const int floats_per_block = 128 * 8;  // 1024

    if (n % floats_per_block == 0) {
        // This shape: 43008 blocks of 128 threads, branch-free, 256-bit ld/st.
        ds_combine_v8<<<n / floats_per_block, 128>>>(a1, a2, out);
    } else {
        int n4 = n >> 2;
        int blocks = (n4 + 511) / 512;
        ds_combine_guarded<<<blocks, 256>>>(
            (const float4*)a1, (const float4*)a2, (float4*)out, n4);
        int tail_start = n4 << 2;
        if (n - tail_start > 0)
            ds_combine_tail<<<1, 128>>>(a1, a2, out, tail_start, n);
    }
}

// round 10
// speedup vs baseline: 1.0032x; 1.0032x over previous
#include <cuda_runtime.h>

// DempsterSchaferCombine — algebraically reduced to a pure elementwise stream:
//   out = (a1-1)*(a2-1)/21 + a1 + a2 - 1
// (Dirichlet strengths S1,S2 and the conflict denom cancel exactly; rel_err
// vs the full reference path is ~8e-8.)
//
// R10: final CTA-granularity step. Measured trend: 256-thr CTAs 70.5us ->
// 128-thr 70.0us (finer retire/launch overlap, occ 77.5->82.7). Now 64-thr
// CTAs with __launch_bounds__(64,32): 32 CTA slots/SM keeps 2048 thr/SM
// while halving drain granularity again. Per-thread shape unchanged: one
// 256-bit v8 chunk per array, 32-bit indexing, branch-free exact tiling
// (n = 44,040,192 = 86016 blocks * 512 floats). DRAM counters pinned at
// ~86% across all one-shot variants — this kernel rides the HBM ceiling.

#define INV_C (1.0f / 21.0f)

__device__ __forceinline__ void ld256_cs(const float* p, float v[8]) {
    asm volatile(
        "ld.global.cs.v8.f32 {%0,%1,%2,%3,%4,%5,%6,%7}, [%8];"
        : "=f"(v[0]), "=f"(v[1]), "=f"(v[2]), "=f"(v[3]),
          "=f"(v[4]), "=f"(v[5]), "=f"(v[6]), "=f"(v[7])
        : "l"(p));
}

__device__ __forceinline__ void st256_cs(float* p, const float v[8]) {
    asm volatile(
        "st.global.cs.v8.f32 [%0], {%1,%2,%3,%4,%5,%6,%7,%8};"
        :: "l"(p),
           "f"(v[0]), "f"(v[1]), "f"(v[2]), "f"(v[3]),
           "f"(v[4]), "f"(v[5]), "f"(v[6]), "f"(v[7])
        : "memory");
}

// Exact path: one 8-float chunk per thread, no predicates, 32-bit indexing.
// Requires n % (64*8) == 0, n < 2^31, 32B-aligned pointers.
__global__ __launch_bounds__(64, 32) void ds_combine_v8_64(
    const float* __restrict__ a1,
    const float* __restrict__ a2,
    float* __restrict__ out)
{
    unsigned int base = (blockIdx.x * 64u + threadIdx.x) * 8u;

    float x[8], y[8], r[8];
    ld256_cs(a1 + base, x);
    ld256_cs(a2 + base, y);

#pragma unroll
    for (int k = 0; k < 8; k++)
        r[k] = fmaf((x[k] - 1.0f) * (y[k] - 1.0f), INV_C, x[k] + y[k] - 1.0f);

    st256_cs(out + base, r);
}

__device__ __forceinline__ float4 ds4(float4 x, float4 y) {
    float4 r;
    r.x = fmaf((x.x - 1.0f) * (y.x - 1.0f), INV_C, x.x + y.x - 1.0f);
    r.y = fmaf((x.y - 1.0f) * (y.y - 1.0f), INV_C, x.y + y.y - 1.0f);
    r.z = fmaf((x.z - 1.0f) * (y.z - 1.0f), INV_C, x.z + y.z - 1.0f);
    r.w = fmaf((x.w - 1.0f) * (y.w - 1.0f), INV_C, x.w + y.w - 1.0f);
    return r;
}

// Guarded fallback (float4) for shapes not divisible by 512 floats/block.
__global__ __launch_bounds__(256, 8) void ds_combine_guarded(
    const float4* __restrict__ a1,
    const float4* __restrict__ a2,
    float4* __restrict__ out,
    int n4)
{
    int i0 = blockIdx.x * 512 + threadIdx.x;
    int i1 = i0 + 256;
    if (i1 < n4) {
        float4 x0 = __ldcs(a1 + i0);
        float4 x1 = __ldcs(a1 + i1);
        float4 y0 = __ldcs(a2 + i0);
        float4 y1 = __ldcs(a2 + i1);
        __stcs(out + i0, ds4(x0, y0));
        __stcs(out + i1, ds4(x1, y1));
    } else if (i0 < n4) {
        float4 x0 = __ldcs(a1 + i0);
        float4 y0 = __ldcs(a2 + i0);
        __stcs(out + i0, ds4(x0, y0));
    }
}

// Scalar tail for n % 4 != 0 (not hit for this shape; kept for safety).
__global__ void ds_combine_tail(
    const float* __restrict__ a1,
    const float* __restrict__ a2,
    float* __restrict__ out,
    int start, int n)
{
    int i = start + blockIdx.x * blockDim.x + threadIdx.x;
    if (i >= n) return;
    float x = a1[i], y = a2[i];
    out[i] = fmaf((x - 1.0f) * (y - 1.0f), INV_C, x + y - 1.0f);
}

extern "C" void kernel_launch(void* const* d_in, const int* in_sizes, int n_in,
                              void* d_out, int out_size)
{
    const float* a1 = (const float*)d_in[0];
    const float* a2 = (const float*)d_in[1];
    float* out = (float*)d_out;

    int n = out_size;                   // 8*21*512*512 = 44,040,192
    const int floats_per_block = 64 * 8;  // 512

    if (n % floats_per_block == 0) {
        // This shape: 86016 blocks of 64 threads, branch-free, 256-bit ld/st.
        ds_combine_v8_64<<<n / floats_per_block, 64>>>(a1, a2, out);
    } else {
        int n4 = n >> 2;
        int blocks = (n4 + 511) / 512;
        ds_combine_guarded<<<blocks, 256>>>(
            (const float4*)a1, (const float4*)a2, (float4*)out, n4);
        int tail_start = n4 << 2;
        if (n - tail_start > 0)
            ds_combine_tail<<<1, 128>>>(a1, a2, out, tail_start, n);
    }
}

// round 11
// speedup vs baseline: 1.0040x; 1.0008x over previous
#include <cuda_runtime.h>

// DempsterSchaferCombine — FINAL (R7/R8 best-measured configuration).
//
// Algebraic collapse: the reference's per-pixel Dirichlet/DS combine
//   S=sum(a), b=(a-1)/S, u=C/S, K, denom=1-K, b_a, u_a, S_a, out=b_a*S_a+1
// cancels exactly (denom, S1, S2 all drop out) to the pure elementwise form
//   out = (a1-1)*(a2-1)/21 + a1 + a2 - 1            (rel_err ~8e-8)
// => minimal traffic: 352 MB read + 176 MB write.
//
// Measured search summary (kernel dur / DRAM%):
//   float4 one-shot 72.3/85.5 · grid-stride loops 76.9/80-82 (rejected)
//   v8 256-thr 70.5/86.0 · v8 128-thr 70.0/86.7 (BEST) · v8 64-thr 71.2/85.2
//   .cs vs .nc loads identical; 32-bit indexing neutral.
// This kernel rides the achieved-HBM ceiling: 528 MB / 70us = 7.5 TB/s.
//
// Shape: one-shot grid, 43008 blocks x 128 threads, one 256-bit v8 chunk per
// thread per array (ld.global.nc.v8 / st.global.cs.v8), branch-free exact
// tiling (44,040,192 = 43008 * 1024), __launch_bounds__(128,16).

#define INV_C (1.0f / 21.0f)

__device__ __forceinline__ void ld256_nc(const float* p, float v[8]) {
    asm volatile(
        "ld.global.nc.v8.f32 {%0,%1,%2,%3,%4,%5,%6,%7}, [%8];"
        : "=f"(v[0]), "=f"(v[1]), "=f"(v[2]), "=f"(v[3]),
          "=f"(v[4]), "=f"(v[5]), "=f"(v[6]), "=f"(v[7])
        : "l"(p));
}

__device__ __forceinline__ void st256_cs(float* p, const float v[8]) {
    asm volatile(
        "st.global.cs.v8.f32 [%0], {%1,%2,%3,%4,%5,%6,%7,%8};"
        :: "l"(p),
           "f"(v[0]), "f"(v[1]), "f"(v[2]), "f"(v[3]),
           "f"(v[4]), "f"(v[5]), "f"(v[6]), "f"(v[7])
        : "memory");
}

// Exact path: one 8-float chunk per thread, no predicates.
// Requires n % (128*8) == 0 and 32B-aligned pointers.
__global__ __launch_bounds__(128, 16) void ds_combine_v8_nc(
    const float* __restrict__ a1,
    const float* __restrict__ a2,
    float* __restrict__ out)
{
    long long base = ((long long)blockIdx.x * 128 + threadIdx.x) * 8;

    float x[8], y[8], r[8];
    ld256_nc(a1 + base, x);
    ld256_nc(a2 + base, y);

#pragma unroll
    for (int k = 0; k < 8; k++)
        r[k] = fmaf((x[k] - 1.0f) * (y[k] - 1.0f), INV_C, x[k] + y[k] - 1.0f);

    st256_cs(out + base, r);
}

__device__ __forceinline__ float4 ds4(float4 x, float4 y) {
    float4 r;
    r.x = fmaf((x.x - 1.0f) * (y.x - 1.0f), INV_C, x.x + y.x - 1.0f);
    r.y = fmaf((x.y - 1.0f) * (y.y - 1.0f), INV_C, x.y + y.y - 1.0f);
    r.z = fmaf((x.z - 1.0f) * (y.z - 1.0f), INV_C, x.z + y.z - 1.0f);
    r.w = fmaf((x.w - 1.0f) * (y.w - 1.0f), INV_C, x.w + y.w - 1.0f);
    return r;
}

// Guarded fallback (float4) for shapes not divisible by 1024 floats/block.
__global__ __launch_bounds__(256, 8) void ds_combine_guarded(
    const float4* __restrict__ a1,
    const float4* __restrict__ a2,
    float4* __restrict__ out,
    int n4)
{
    int i0 = blockIdx.x * 512 + threadIdx.x;
    int i1 = i0 + 256;
    if (i1 < n4) {
        float4 x0 = __ldcs(a1 + i0);
        float4 x1 = __ldcs(a1 + i1);
        float4 y0 = __ldcs(a2 + i0);
        float4 y1 = __ldcs(a2 + i1);
        __stcs(out + i0, ds4(x0, y0));
        __stcs(out + i1, ds4(x1, y1));
    } else if (i0 < n4) {
        float4 x0 = __ldcs(a1 + i0);
        float4 y0 = __ldcs(a2 + i0);
        __stcs(out + i0, ds4(x0, y0));
    }
}

// Scalar tail for n % 4 != 0 (not hit for this shape; kept for safety).
__global__ void ds_combine_tail(
    const float* __restrict__ a1,
    const float* __restrict__ a2,
    float* __restrict__ out,
    int start, int n)
{
    int i = start + blockIdx.x * blockDim.x + threadIdx.x;
    if (i >= n) return;
    float x = a1[i], y = a2[i];
    out[i] = fmaf((x - 1.0f) * (y - 1.0f), INV_C, x + y - 1.0f);
}

extern "C" void kernel_launch(void* const* d_in, const int* in_sizes, int n_in,
                              void* d_out, int out_size)
{
    const float* a1 = (const float*)d_in[0];
    const float* a2 = (const float*)d_in[1];
    float* out = (float*)d_out;

    int n = out_size;                    // 8*21*512*512 = 44,040,192
    const int floats_per_block = 128 * 8;  // 1024

    if (n % floats_per_block == 0) {
        // This shape: 43008 blocks of 128 threads, branch-free, 256-bit ld/st.
        ds_combine_v8_nc<<<n / floats_per_block, 128>>>(a1, a2, out);
    } else {
        int n4 = n >> 2;
        int blocks = (n4 + 511) / 512;
        ds_combine_guarded<<<blocks, 256>>>(
            (const float4*)a1, (const float4*)a2, (float4*)out, n4);
        int tail_start = n4 << 2;
        if (n - tail_start > 0)
            ds_combine_tail<<<1, 128>>>(a1, a2, out, tail_start, n);
    }
}

// round 12
// speedup vs baseline: 1.0089x; 1.0048x over previous
#include <cuda_runtime.h>

// DempsterSchaferCombine — FINAL converged kernel.
//
// Algebraic collapse: the reference's per-pixel Dirichlet/DS combine
//   S=sum(a), b=(a-1)/S, u=C/S, K, denom=1-K, b_a, u_a, S_a, out=b_a*S_a+1
// cancels exactly (denom, S1, S2 all drop out) to the pure elementwise form
//   out = (a1-1)*(a2-1)/21 + a1 + a2 - 1            (rel_err ~8e-8)
// => minimal traffic: 352 MB read + 176 MB write.
//
// Converged configuration (11 rounds of measurement):
//   one-shot grid (grid-stride loops cost 6-8% DRAM%), 128-thr CTAs
//   (256-thr: 70.5us, 128-thr: 69.7-70.0us, 64-thr: 71.2us), one 256-bit v8
//   chunk per thread per array, ld.global.nc.v8 loads + st.global.cs.v8
//   stores, 32-bit indexing (alu 4%->0.8%), branch-free exact tiling
//   (44,040,192 = 43008 blocks * 1024 floats), __launch_bounds__(128,16).
//   Measured: ~69.7us kernel, DRAM counters 86.9%, 7.5 TB/s effective.

#define INV_C (1.0f / 21.0f)

__device__ __forceinline__ void ld256_nc(const float* p, float v[8]) {
    asm volatile(
        "ld.global.nc.v8.f32 {%0,%1,%2,%3,%4,%5,%6,%7}, [%8];"
        : "=f"(v[0]), "=f"(v[1]), "=f"(v[2]), "=f"(v[3]),
          "=f"(v[4]), "=f"(v[5]), "=f"(v[6]), "=f"(v[7])
        : "l"(p));
}

__device__ __forceinline__ void st256_cs(float* p, const float v[8]) {
    asm volatile(
        "st.global.cs.v8.f32 [%0], {%1,%2,%3,%4,%5,%6,%7,%8};"
        :: "l"(p),
           "f"(v[0]), "f"(v[1]), "f"(v[2]), "f"(v[3]),
           "f"(v[4]), "f"(v[5]), "f"(v[6]), "f"(v[7])
        : "memory");
}

// Exact path: one 8-float chunk per thread, no predicates, 32-bit indexing.
// Requires n % (128*8) == 0, n < 2^31, 32B-aligned pointers.
__global__ __launch_bounds__(128, 16) void ds_combine_v8_nc(
    const float* __restrict__ a1,
    const float* __restrict__ a2,
    float* __restrict__ out)
{
    unsigned int base = (blockIdx.x * 128u + threadIdx.x) * 8u;

    float x[8], y[8], r[8];
    ld256_nc(a1 + base, x);
    ld256_nc(a2 + base, y);

#pragma unroll
    for (int k = 0; k < 8; k++)
        r[k] = fmaf((x[k] - 1.0f) * (y[k] - 1.0f), INV_C, x[k] + y[k] - 1.0f);

    st256_cs(out + base, r);
}

__device__ __forceinline__ float4 ds4(float4 x, float4 y) {
    float4 r;
    r.x = fmaf((x.x - 1.0f) * (y.x - 1.0f), INV_C, x.x + y.x - 1.0f);
    r.y = fmaf((x.y - 1.0f) * (y.y - 1.0f), INV_C, x.y + y.y - 1.0f);
    r.z = fmaf((x.z - 1.0f) * (y.z - 1.0f), INV_C, x.z + y.z - 1.0f);
    r.w = fmaf((x.w - 1.0f) * (y.w - 1.0f), INV_C, x.w + y.w - 1.0f);
    return r;
}

// Guarded fallback (float4) for shapes not divisible by 1024 floats/block.
__global__ __launch_bounds__(256, 8) void ds_combine_guarded(
    const float4* __restrict__ a1,
    const float4* __restrict__ a2,
    float4* __restrict__ out,
    int n4)
{
    int i0 = blockIdx.x * 512 + threadIdx.x;
    int i1 = i0 + 256;
    if (i1 < n4) {
        float4 x0 = __ldcs(a1 + i0);
        float4 x1 = __ldcs(a1 + i1);
        float4 y0 = __ldcs(a2 + i0);
        float4 y1 = __ldcs(a2 + i1);
        __stcs(out + i0, ds4(x0, y0));
        __stcs(out + i1, ds4(x1, y1));
    } else if (i0 < n4) {
        float4 x0 = __ldcs(a1 + i0);
        float4 y0 = __ldcs(a2 + i0);
        __stcs(out + i0, ds4(x0, y0));
    }
}

// Scalar tail for n % 4 != 0 (not hit for this shape; kept for safety).
__global__ void ds_combine_tail(
    const float* __restrict__ a1,
    const float* __restrict__ a2,
    float* __restrict__ out,
    int start, int n)
{
    int i = start + blockIdx.x * blockDim.x + threadIdx.x;
    if (i >= n) return;
    float x = a1[i], y = a2[i];
    out[i] = fmaf((x - 1.0f) * (y - 1.0f), INV_C, x + y - 1.0f);
}

extern "C" void kernel_launch(void* const* d_in, const int* in_sizes, int n_in,
                              void* d_out, int out_size)
{
    const float* a1 = (const float*)d_in[0];
    const float* a2 = (const float*)d_in[1];
    float* out = (float*)d_out;

    int n = out_size;                    // 8*21*512*512 = 44,040,192
    const int floats_per_block = 128 * 8;  // 1024

    if (n % floats_per_block == 0) {
        // This shape: 43008 blocks of 128 threads, branch-free, 256-bit ld/st.
        ds_combine_v8_nc<<<n / floats_per_block, 128>>>(a1, a2, out);
    } else {
        int n4 = n >> 2;
        int blocks = (n4 + 511) / 512;
        ds_combine_guarded<<<blocks, 256>>>(
            (const float4*)a1, (const float4*)a2, (float4*)out, n4);
        int tail_start = n4 << 2;
        if (n - tail_start > 0)
            ds_combine_tail<<<1, 128>>>(a1, a2, out, tail_start, n);
    }
}